// round 12
// baseline (speedup 1.0000x reference)
#include <cuda_runtime.h>
#include <math.h>
#include <stdint.h>

constexpr int B_=4, S_=2048, D_=1024, H_=16, DFF_=4096, L_=6;
constexpr int BS_ = B_*S_;

// ---------------- scratch ----------------
__device__ float g_h  [(size_t)BS_*D_];
__device__ float g_hr [(size_t)BS_*D_];
__device__ float g_q  [(size_t)BS_*D_];
__device__ float g_k  [(size_t)BS_*D_];
__device__ float g_v  [(size_t)BS_*D_];
__device__ float g_ctx[(size_t)BS_*D_];
__device__ float g_p  [(size_t)BS_*D_];
__device__ float g_ff [(size_t)BS_*DFF_];
__device__ float g_cwq[(size_t)L_*D_*D_];
__device__ float g_cwk[(size_t)L_*D_*D_];
__device__ float g_cwv[(size_t)L_*D_*D_];
__device__ float g_cwo[(size_t)L_*D_*D_];
__device__ float g_cw1[(size_t)L_*D_*DFF_];
__device__ float g_cw2[(size_t)L_*DFF_*D_];

// ---------------- helpers ----------------
__device__ __forceinline__ uint32_t f2tf32(float x) {
    uint32_t r; asm("cvt.rna.tf32.f32 %0, %1;" : "=r"(r) : "f"(x)); return r;
}
__device__ __forceinline__ float rnd32(float x) {
    return __uint_as_float(f2tf32(x));
}
__device__ __forceinline__ void mma_tf32(float* c, const uint32_t* a,
                                         const uint32_t* b) {
    asm volatile(
        "mma.sync.aligned.m16n8k8.row.col.f32.tf32.tf32.f32 "
        "{%0,%1,%2,%3}, {%4,%5,%6,%7}, {%8,%9}, {%0,%1,%2,%3};\n"
        : "+f"(c[0]), "+f"(c[1]), "+f"(c[2]), "+f"(c[3])
        : "r"(a[0]), "r"(a[1]), "r"(a[2]), "r"(a[3]), "r"(b[0]), "r"(b[1]));
}
__device__ __forceinline__ void cp_async16(uint32_t dst, const void* src) {
    asm volatile("cp.async.cg.shared.global [%0], [%1], 16;\n"
                 :: "r"(dst), "l"(src));
}
#define CP_COMMIT() asm volatile("cp.async.commit_group;\n" ::: "memory")
#define CP_WAIT(N)  asm volatile("cp.async.wait_group %0;\n" :: "n"(N) : "memory")
#define LDSM_X4(r0, r1, r2, r3, addr) \
    asm volatile("ldmatrix.sync.aligned.m8n8.x4.shared.b16 {%0,%1,%2,%3}, [%4];" \
                 : "=r"(r0), "=r"(r1), "=r"(r2), "=r"(r3) : "r"(addr))

// ---------------- fused weight pre-round ----------------
__global__ void round4_kernel(const float* s0, const float* s1,
                              const float* s2, const float* s3,
                              float* d0, float* d1, float* d2, float* d3,
                              int n4) {
    int i = blockIdx.x * blockDim.x + threadIdx.x;
    if (i >= n4) return;
    const float* s; float* d;
    switch (blockIdx.y) {
        case 0: s = s0; d = d0; break;
        case 1: s = s1; d = d1; break;
        case 2: s = s2; d = d2; break;
        default: s = s3; d = d3; break;
    }
    float4 v = ((const float4*)s)[i];
    v.x = rnd32(v.x); v.y = rnd32(v.y); v.z = rnd32(v.z); v.w = rnd32(v.w);
    ((float4*)d)[i] = v;
}
__global__ void round2_kernel(const float* s0, const float* s1,
                              float* d0, float* d1, int n4) {
    int i = blockIdx.x * blockDim.x + threadIdx.x;
    if (i >= n4) return;
    const float* s = blockIdx.y ? s1 : s0;
    float* d       = blockIdx.y ? d1 : d0;
    float4 v = ((const float4*)s)[i];
    v.x = rnd32(v.x); v.y = rnd32(v.y); v.z = rnd32(v.z); v.w = rnd32(v.w);
    ((float4*)d)[i] = v;
}

// ---------------- embedding + PE ----------------
__global__ void embed_kernel(const int* __restrict__ x,
                             const float* __restrict__ emb,
                             float* __restrict__ h, float* __restrict__ hr) {
    int idx = blockIdx.x * blockDim.x + threadIdx.x;
    int row = idx >> 10, d = idx & (D_ - 1);
    int tok = x[row], s = row & (S_ - 1);
    float val = emb[(size_t)tok * D_ + d] * 32.0f;
    float div = expf((float)(d & ~1) * (-0.00899447301960227f));
    float ang = (float)s * div;
    float v = val + ((d & 1) ? cosf(ang) : sinf(ang));
    h[idx]  = v;
    hr[idx] = rnd32(v);
}

// ---------------- pipelined tf32 GEMM: 64x128 tile, 3 CTAs/SM -------------
// 256 threads = 8 warps (2x4), warp tile 32x32, 2 smem stages.
constexpr int STAGES  = 2;
constexpr int ALD     = 36;
constexpr int BLD     = 132;
constexpr int A_STAGE = 64 * ALD;          // 2304 floats
constexpr int B_STAGE = 32 * BLD;          // 4224 floats
constexpr int STAGE_F = A_STAGE + B_STAGE; // 6528
constexpr int GEMM_SMEM_BYTES = STAGES * STAGE_F * 4;   // 52224 B

template<int RELU, int ROUND>
__device__ __forceinline__ void gemm_body(
    const float* __restrict__ A, const float* __restrict__ W,
    const float* __restrict__ bias, float* __restrict__ C, int N, int K) {
    extern __shared__ float smf[];
    const uint32_t smem_base = (uint32_t)__cvta_generic_to_shared(smf);

    const int t    = threadIdx.x;
    const int m0   = blockIdx.y * 64;
    const int n0   = blockIdx.x * 128;
    const int warp = t >> 5, lane = t & 31;
    const int wm   = warp >> 2, wn = warp & 3;   // 2x4; warp tile 32x32
    const int g    = lane >> 2, tg = lane & 3;
    const int li   = lane & 7, sel = lane >> 3;

    const int aR  = t >> 3;           // A rows aR, aR+32
    const int aK4 = (t & 7) << 2;
    const int bK  = t >> 5;           // B k-rows bK, +8, +16, +24
    const int bN4 = (t & 31) << 2;

    const float* Ag = A + (size_t)m0 * K;
    const float* Bg = W + n0;

    float acc[2][4][4];
    #pragma unroll
    for (int i = 0; i < 2; i++)
        #pragma unroll
        for (int j = 0; j < 4; j++)
            #pragma unroll
            for (int r = 0; r < 4; r++) acc[i][j][r] = 0.0f;

    auto prefetch = [&](int kt, int stage) {
        const int k0 = kt << 5;
        uint32_t As = smem_base + (stage * STAGE_F) * 4;
        uint32_t Bs = As + A_STAGE * 4;
        cp_async16(As + (aR * ALD + aK4) * 4,
                   Ag + (size_t)aR * K + k0 + aK4);
        cp_async16(As + ((aR + 32) * ALD + aK4) * 4,
                   Ag + (size_t)(aR + 32) * K + k0 + aK4);
        #pragma unroll
        for (int i = 0; i < 4; i++) {
            int kk = bK + i * 8;
            cp_async16(Bs + (kk * BLD + bN4) * 4,
                       Bg + (size_t)(k0 + kk) * N + bN4);
        }
    };

    const int ldsmRow = wm * 32 + li + 8 * (sel & 1);
    const int ldsmCol = 4 * (sel >> 1);

    auto compute = [&](int stage) {
        const uint32_t As_u = smem_base + (stage * STAGE_F) * 4;
        const uint32_t* Bs = (const uint32_t*)(smf + stage * STAGE_F) + A_STAGE;
        uint32_t aBase[2];
        #pragma unroll
        for (int mf = 0; mf < 2; mf++)
            aBase[mf] = As_u + ((ldsmRow + mf * 16) * ALD + ldsmCol) * 4;
        #pragma unroll
        for (int ks = 0; ks < 4; ks++) {
            const int k8 = ks << 3;
            uint32_t a[2][4], b[4][2];
            #pragma unroll
            for (int mf = 0; mf < 2; mf++)
                LDSM_X4(a[mf][0], a[mf][1], a[mf][2], a[mf][3],
                        aBase[mf] + k8 * 4);
            #pragma unroll
            for (int nf = 0; nf < 4; nf++) {
                const int nb = wn * 32 + nf * 8 + g;
                b[nf][0] = Bs[(k8 + tg)     * BLD + nb];
                b[nf][1] = Bs[(k8 + tg + 4) * BLD + nb];
            }
            #pragma unroll
            for (int mf = 0; mf < 2; mf++)
                #pragma unroll
                for (int nf = 0; nf < 4; nf++)
                    mma_tf32(acc[mf][nf], a[mf], b[nf]);
        }
    };

    const int nk = K >> 5;
    prefetch(0, 0); CP_COMMIT();
    prefetch(1, 1); CP_COMMIT();

    for (int kt = 0; kt < nk; kt++) {
        CP_WAIT(1);
        __syncthreads();
        compute(kt & 1);
        __syncthreads();
        if (kt + 2 < nk) prefetch(kt + 2, kt & 1);
        CP_COMMIT();   // unconditional: keeps group ordering for CP_WAIT(1)
    }

    #pragma unroll
    for (int mf = 0; mf < 2; mf++) {
        int r0 = m0 + wm * 32 + mf * 16 + g;
        int r1 = r0 + 8;
        #pragma unroll
        for (int nf = 0; nf < 4; nf++) {
            int col = n0 + wn * 32 + nf * 8 + tg * 2;
            float2 bb = *(const float2*)&bias[col];
            float2 o0, o1;
            o0.x = acc[mf][nf][0] + bb.x;
            o0.y = acc[mf][nf][1] + bb.y;
            o1.x = acc[mf][nf][2] + bb.x;
            o1.y = acc[mf][nf][3] + bb.y;
            if (RELU) {
                o0.x = fmaxf(o0.x, 0.f); o0.y = fmaxf(o0.y, 0.f);
                o1.x = fmaxf(o1.x, 0.f); o1.y = fmaxf(o1.y, 0.f);
            }
            if (ROUND) {
                o0.x = rnd32(o0.x); o0.y = rnd32(o0.y);
                o1.x = rnd32(o1.x); o1.y = rnd32(o1.y);
            }
            *(float2*)&C[(size_t)r0 * N + col] = o0;
            *(float2*)&C[(size_t)r1 * N + col] = o1;
        }
    }
}

template<int RELU, int ROUND>
__global__ __launch_bounds__(256, 3) void gemm_tf32(
    const float* __restrict__ A, const float* __restrict__ W,
    const float* __restrict__ bias, float* __restrict__ C, int N, int K) {
    gemm_body<RELU, ROUND>(A, W, bias, C, N, K);
}

__global__ __launch_bounds__(256, 3) void gemm_qkv(
    const float* __restrict__ A,
    const float* __restrict__ wq, const float* __restrict__ bq,
    const float* __restrict__ wk, const float* __restrict__ bk,
    const float* __restrict__ wv, const float* __restrict__ bv,
    float* __restrict__ oq, float* __restrict__ ok, float* __restrict__ ov) {
    const float* W; const float* bias; float* C;
    if (blockIdx.z == 0)      { W = wq; bias = bq; C = oq; }
    else if (blockIdx.z == 1) { W = wk; bias = bk; C = ok; }
    else                      { W = wv; bias = bv; C = ov; }
    gemm_body<0, 1>(A, W, bias, C, D_, D_);
}

// ---------------- flash attention: 64-wide KV tiles, 2 CTAs/SM ------------
constexpr int AKLD = 68, AVLD = 72, APLD = 68;
constexpr int TN_   = 64;
constexpr int AK_BUF = TN_ * AKLD;
constexpr int AV_BUF = TN_ * AVLD;
constexpr int ATTN_SMEM =
    (2 * AK_BUF + 2 * AV_BUF + 128 * APLD) * 4 + S_;

__global__ __launch_bounds__(256, 2) void attn_mma(
    const float* __restrict__ Q, const float* __restrict__ K,
    const float* __restrict__ V, const int* __restrict__ mask,
    float* __restrict__ ctx) {
    extern __shared__ float smf[];
    float*    Ksf = smf;
    float*    Vsf = smf + 2 * AK_BUF;
    uint32_t* Ps  = (uint32_t*)(Vsf + 2 * AV_BUF);
    char*     msk = (char*)(Ps + 128 * APLD);
    const uint32_t sb   = (uint32_t)__cvta_generic_to_shared(smf);
    const uint32_t sbV  = sb + 2 * AK_BUF * 4;
    const uint32_t sbP  = sbV + 2 * AV_BUF * 4;

    const int qt = blockIdx.x, h = blockIdx.y, b = blockIdx.z;
    const int t = threadIdx.x, w = t >> 5, lane = t & 31;
    const int g = lane >> 2, tg = lane & 3;
    const int li = lane & 7, sel = lane >> 3;
    const int r0 = w * 16 + g, r1 = r0 + 8;

    for (int i = t; i < S_; i += 256) msk[i] = (char)mask[b * S_ + i];
    for (int i = t; i < 128 * 16; i += 256) {
        int r = i >> 4, c4 = (i & 15) << 2;
        float4 qv = *(const float4*)&Q[(size_t)(b * S_ + qt * 128 + r) * D_ +
                                       h * 64 + c4];
        float* dst = &Ksf[r * AKLD + c4];
        dst[0] = qv.x; dst[1] = qv.y; dst[2] = qv.z; dst[3] = qv.w;
    }
    __syncthreads();
    uint32_t qr[8][4];
    {
        const uint32_t* Qs = (const uint32_t*)Ksf;
        #pragma unroll
        for (int kb8 = 0; kb8 < 8; kb8++) {
            int kb = kb8 * 8;
            qr[kb8][0] = Qs[r0 * AKLD + kb + tg];
            qr[kb8][1] = Qs[r1 * AKLD + kb + tg];
            qr[kb8][2] = Qs[r0 * AKLD + kb + tg + 4];
            qr[kb8][3] = Qs[r1 * AKLD + kb + tg + 4];
        }
    }
    __syncthreads();

    auto prefetch = [&](int kt, int buf) {
        const uint32_t kb = sb  + buf * AK_BUF * 4;
        const uint32_t vb = sbV + buf * AV_BUF * 4;
        #pragma unroll
        for (int i = 0; i < 4; i++) {
            int chunk = t + i * 256;
            int r = chunk >> 4, c4 = (chunk & 15) << 2;
            size_t gofs = (size_t)(b * S_ + kt * TN_ + r) * D_ + h * 64 + c4;
            cp_async16(kb + (r * AKLD + c4) * 4, K + gofs);
            cp_async16(vb + (r * AVLD + c4) * 4, V + gofs);
        }
    };

    prefetch(0, 0); CP_COMMIT();
    prefetch(1, 1); CP_COMMIT();

    float m_i[2] = {-INFINITY, -INFINITY}, l_i[2] = {0.f, 0.f};
    float o[8][4];
    #pragma unroll
    for (int nf = 0; nf < 8; nf++)
        #pragma unroll
        for (int r = 0; r < 4; r++) o[nf][r] = 0.f;

    const uint32_t pBase =
        sbP + ((w * 16 + li + 8 * (sel & 1)) * APLD + 4 * (sel >> 1)) * 4;

    const int NT = S_ / TN_;
    for (int kt = 0; kt < NT; kt++) {
        CP_WAIT(1);
        __syncthreads();
        const uint32_t* Kc = (const uint32_t*)(Ksf + (kt & 1) * AK_BUF);
        const uint32_t* Vc = (const uint32_t*)(Vsf + (kt & 1) * AV_BUF);

        float s[8][4];
        #pragma unroll
        for (int nf = 0; nf < 8; nf++)
            #pragma unroll
            for (int r = 0; r < 4; r++) s[nf][r] = 0.f;
        #pragma unroll
        for (int kb8 = 0; kb8 < 8; kb8++) {
            int kb = kb8 * 8;
            #pragma unroll
            for (int nf = 0; nf < 8; nf++) {
                uint32_t bf[2];
                bf[0] = Kc[(nf * 8 + g) * AKLD + kb + tg];
                bf[1] = Kc[(nf * 8 + g) * AKLD + kb + tg + 4];
                mma_tf32(s[nf], qr[kb8], bf);
            }
        }

        float mx0 = -INFINITY, mx1 = -INFINITY;
        #pragma unroll
        for (int nf = 0; nf < 8; nf++) {
            int c = kt * TN_ + nf * 8 + 2 * tg;
            s[nf][0] *= 0.125f; s[nf][1] *= 0.125f;
            s[nf][2] *= 0.125f; s[nf][3] *= 0.125f;
            if (msk[c] == 0)     { s[nf][0] = -1e9f; s[nf][2] = -1e9f; }
            if (msk[c + 1] == 0) { s[nf][1] = -1e9f; s[nf][3] = -1e9f; }
            mx0 = fmaxf(mx0, fmaxf(s[nf][0], s[nf][1]));
            mx1 = fmaxf(mx1, fmaxf(s[nf][2], s[nf][3]));
        }
        #pragma unroll
        for (int off = 1; off <= 2; off <<= 1) {
            mx0 = fmaxf(mx0, __shfl_xor_sync(0xffffffffu, mx0, off));
            mx1 = fmaxf(mx1, __shfl_xor_sync(0xffffffffu, mx1, off));
        }
        float mn0 = fmaxf(m_i[0], mx0), mn1 = fmaxf(m_i[1], mx1);
        float corr0 = __expf(m_i[0] - mn0), corr1 = __expf(m_i[1] - mn1);
        m_i[0] = mn0; m_i[1] = mn1;

        float rs0 = 0.f, rs1 = 0.f;
        #pragma unroll
        for (int nf = 0; nf < 8; nf++) {
            float p0 = __expf(s[nf][0] - mn0), p1 = __expf(s[nf][1] - mn0);
            float p2 = __expf(s[nf][2] - mn1), p3 = __expf(s[nf][3] - mn1);
            rs0 += p0 + p1; rs1 += p2 + p3;
            *(uint2*)&Ps[r0 * APLD + nf * 8 + 2 * tg] =
                make_uint2(f2tf32(p0), f2tf32(p1));
            *(uint2*)&Ps[r1 * APLD + nf * 8 + 2 * tg] =
                make_uint2(f2tf32(p2), f2tf32(p3));
        }
        #pragma unroll
        for (int off = 1; off <= 2; off <<= 1) {
            rs0 += __shfl_xor_sync(0xffffffffu, rs0, off);
            rs1 += __shfl_xor_sync(0xffffffffu, rs1, off);
        }
        l_i[0] = l_i[0] * corr0 + rs0;
        l_i[1] = l_i[1] * corr1 + rs1;
        #pragma unroll
        for (int nf = 0; nf < 8; nf++) {
            o[nf][0] *= corr0; o[nf][1] *= corr0;
            o[nf][2] *= corr1; o[nf][3] *= corr1;
        }
        __syncwarp();

        #pragma unroll
        for (int kb = 0; kb < TN_; kb += 8) {
            uint32_t a[4];
            LDSM_X4(a[0], a[1], a[2], a[3], pBase + kb * 4);
            #pragma unroll
            for (int nf = 0; nf < 8; nf++) {
                uint32_t bf[2];
                bf[0] = Vc[(kb + tg) * AVLD + nf * 8 + g];
                bf[1] = Vc[(kb + tg + 4) * AVLD + nf * 8 + g];
                mma_tf32(o[nf], a, bf);
            }
        }
        __syncthreads();
        if (kt + 2 < NT) prefetch(kt + 2, kt & 1);
        CP_COMMIT();
    }

    float inv0 = 1.f / l_i[0], inv1 = 1.f / l_i[1];
    size_t row0 = (size_t)(b * S_ + qt * 128 + r0) * D_ + h * 64;
    size_t row1 = (size_t)(b * S_ + qt * 128 + r1) * D_ + h * 64;
    #pragma unroll
    for (int nf = 0; nf < 8; nf++) {
        int col = nf * 8 + 2 * tg;
        *(float2*)&ctx[row0 + col] =
            make_float2(rnd32(o[nf][0] * inv0), rnd32(o[nf][1] * inv0));
        *(float2*)&ctx[row1 + col] =
            make_float2(rnd32(o[nf][2] * inv1), rnd32(o[nf][3] * inv1));
    }
}

// ---------------- fused residual + LayerNorm ----------------
template<int WR>
__global__ __launch_bounds__(256) void ln_kernel(
    const float* __restrict__ a, const float* __restrict__ r,
    const float* __restrict__ g, const float* __restrict__ be,
    float* __restrict__ out, float* __restrict__ outr) {
    int row = blockIdx.x, t = threadIdx.x;
    float4 x = ((const float4*)a)[(size_t)row * 256 + t];
    if (r) {
        float4 y = ((const float4*)r)[(size_t)row * 256 + t];
        x.x += y.x; x.y += y.y; x.z += y.z; x.w += y.w;
    }
    float s  = x.x + x.y + x.z + x.w;
    float ss = x.x*x.x + x.y*x.y + x.z*x.z + x.w*x.w;
    #pragma unroll
    for (int off = 16; off; off >>= 1) {
        s  += __shfl_xor_sync(0xffffffffu, s,  off);
        ss += __shfl_xor_sync(0xffffffffu, ss, off);
    }
    __shared__ float wsum[8], wsq[8];
    int warp = t >> 5, lane = t & 31;
    if (lane == 0) { wsum[warp] = s; wsq[warp] = ss; }
    __syncthreads();
    s = 0.f; ss = 0.f;
    #pragma unroll
    for (int i = 0; i < 8; i++) { s += wsum[i]; ss += wsq[i]; }
    float mean = s * (1.f/1024.f);
    float var  = ss * (1.f/1024.f) - mean*mean;
    float rstd = rsqrtf(var + 1e-5f);
    float4 gg = ((const float4*)g)[t];
    float4 bb = ((const float4*)be)[t];
    float4 o;
    o.x = (x.x - mean)*rstd*gg.x + bb.x;
    o.y = (x.y - mean)*rstd*gg.y + bb.y;
    o.z = (x.z - mean)*rstd*gg.z + bb.z;
    o.w = (x.w - mean)*rstd*gg.w + bb.w;
    ((float4*)out)[(size_t)row * 256 + t] = o;
    if (WR) {
        float4 q;
        q.x = rnd32(o.x); q.y = rnd32(o.y); q.z = rnd32(o.z); q.w = rnd32(o.w);
        ((float4*)outr)[(size_t)row * 256 + t] = q;
    }
}

// ---------------- launch ----------------
extern "C" void kernel_launch(void* const* d_in, const int* in_sizes, int n_in,
                              void* d_out, int out_size) {
    (void)in_sizes; (void)n_in; (void)out_size;
    const int*   x    = (const int*)  d_in[0];
    const int*   mask = (const int*)  d_in[1];
    const float* emb  = (const float*)d_in[2];
    const float* wq   = (const float*)d_in[3];
    const float* bq   = (const float*)d_in[4];
    const float* wk   = (const float*)d_in[5];
    const float* bk   = (const float*)d_in[6];
    const float* wv   = (const float*)d_in[7];
    const float* bv   = (const float*)d_in[8];
    const float* wo   = (const float*)d_in[9];
    const float* bo   = (const float*)d_in[10];
    const float* w1   = (const float*)d_in[11];
    const float* b1   = (const float*)d_in[12];
    const float* w2   = (const float*)d_in[13];
    const float* b2   = (const float*)d_in[14];
    const float* g1   = (const float*)d_in[15];
    const float* be1  = (const float*)d_in[16];
    const float* g2   = (const float*)d_in[17];
    const float* be2  = (const float*)d_in[18];
    const float* gf   = (const float*)d_in[19];
    const float* bf   = (const float*)d_in[20];
    float* out = (float*)d_out;

    float *gh, *ghr, *gq, *gk, *gv, *gctx, *gp, *gff;
    float *cwq, *cwk, *cwv, *cwo, *cw1, *cw2;
    cudaGetSymbolAddress((void**)&gh,   g_h);
    cudaGetSymbolAddress((void**)&ghr,  g_hr);
    cudaGetSymbolAddress((void**)&gq,   g_q);
    cudaGetSymbolAddress((void**)&gk,   g_k);
    cudaGetSymbolAddress((void**)&gv,   g_v);
    cudaGetSymbolAddress((void**)&gctx, g_ctx);
    cudaGetSymbolAddress((void**)&gp,   g_p);
    cudaGetSymbolAddress((void**)&gff,  g_ff);
    cudaGetSymbolAddress((void**)&cwq,  g_cwq);
    cudaGetSymbolAddress((void**)&cwk,  g_cwk);
    cudaGetSymbolAddress((void**)&cwv,  g_cwv);
    cudaGetSymbolAddress((void**)&cwo,  g_cwo);
    cudaGetSymbolAddress((void**)&cw1,  g_cw1);
    cudaGetSymbolAddress((void**)&cw2,  g_cw2);

    cudaFuncSetAttribute(attn_mma,
        cudaFuncAttributeMaxDynamicSharedMemorySize, ATTN_SMEM);
    cudaFuncSetAttribute(gemm_tf32<0,0>,
        cudaFuncAttributeMaxDynamicSharedMemorySize, GEMM_SMEM_BYTES);
    cudaFuncSetAttribute(gemm_tf32<0,1>,
        cudaFuncAttributeMaxDynamicSharedMemorySize, GEMM_SMEM_BYTES);
    cudaFuncSetAttribute(gemm_tf32<1,1>,
        cudaFuncAttributeMaxDynamicSharedMemorySize, GEMM_SMEM_BYTES);
    cudaFuncSetAttribute(gemm_qkv,
        cudaFuncAttributeMaxDynamicSharedMemorySize, GEMM_SMEM_BYTES);

    const int nDD = L_ * D_ * D_ / 4, nDF = L_ * D_ * DFF_ / 4;
    round4_kernel<<<dim3((nDD + 255) / 256, 4), 256>>>(
        wq, wk, wv, wo, cwq, cwk, cwv, cwo, nDD);
    round2_kernel<<<dim3((nDF + 255) / 256, 2), 256>>>(
        w1, w2, cw1, cw2, nDF);

    embed_kernel<<<(BS_ * D_) / 256, 256>>>(x, emb, gh, ghr);

    for (int l = 0; l < L_; l++) {
        const size_t wOff = (size_t)l * D_ * D_;
        const size_t fOff = (size_t)l * D_ * DFF_;
        gemm_qkv<<<dim3(8, 128, 3), 256, GEMM_SMEM_BYTES>>>(
            ghr, cwq + wOff, bq + l * D_, cwk + wOff, bk + l * D_,
            cwv + wOff, bv + l * D_, gq, gk, gv);
        attn_mma<<<dim3(S_ / 128, H_, B_), 256, ATTN_SMEM>>>(
            gq, gk, gv, mask, gctx);
        gemm_tf32<0,0><<<dim3(8, 128), 256, GEMM_SMEM_BYTES>>>(
            gctx, cwo + wOff, bo + l * D_, gp, D_, D_);
        ln_kernel<1><<<BS_, 256>>>(gh, gp, g1 + l * D_, be1 + l * D_, gh, ghr);
        gemm_tf32<1,1><<<dim3(32, 128), 256, GEMM_SMEM_BYTES>>>(
            ghr, cw1 + fOff, b1 + l * DFF_, gff, DFF_, D_);
        gemm_tf32<0,0><<<dim3(8, 128), 256, GEMM_SMEM_BYTES>>>(
            gff, cw2 + fOff, b2 + l * D_, gp, D_, DFF_);
        ln_kernel<1><<<BS_, 256>>>(gh, gp, g2 + l * D_, be2 + l * D_, gh, ghr);
    }
    ln_kernel<0><<<BS_, 256>>>(gh, nullptr, gf, bf, out, nullptr);
}

// round 13
// speedup vs baseline: 1.1869x; 1.1869x over previous
#include <cuda_runtime.h>
#include <math.h>
#include <stdint.h>

constexpr int B_=4, S_=2048, D_=1024, H_=16, DFF_=4096, L_=6;
constexpr int BS_ = B_*S_;

// ---------------- scratch ----------------
__device__ float g_h  [(size_t)BS_*D_];
__device__ float g_hr [(size_t)BS_*D_];
__device__ float g_q  [(size_t)BS_*D_];
__device__ float g_k  [(size_t)BS_*D_];
__device__ float g_v  [(size_t)BS_*D_];
__device__ float g_ctx[(size_t)BS_*D_];
__device__ float g_p  [(size_t)BS_*D_];
__device__ float g_ff [(size_t)BS_*DFF_];
__device__ float g_cwq[(size_t)L_*D_*D_];
__device__ float g_cwk[(size_t)L_*D_*D_];
__device__ float g_cwv[(size_t)L_*D_*D_];
__device__ float g_cwo[(size_t)L_*D_*D_];
__device__ float g_cw1[(size_t)L_*D_*DFF_];
__device__ float g_cw2[(size_t)L_*DFF_*D_];

// ---------------- helpers ----------------
__device__ __forceinline__ uint32_t f2tf32(float x) {
    uint32_t r; asm("cvt.rna.tf32.f32 %0, %1;" : "=r"(r) : "f"(x)); return r;
}
__device__ __forceinline__ float rnd32(float x) {
    return __uint_as_float(f2tf32(x));
}
__device__ __forceinline__ void mma_tf32(float* c, const uint32_t* a,
                                         const uint32_t* b) {
    asm volatile(
        "mma.sync.aligned.m16n8k8.row.col.f32.tf32.tf32.f32 "
        "{%0,%1,%2,%3}, {%4,%5,%6,%7}, {%8,%9}, {%0,%1,%2,%3};\n"
        : "+f"(c[0]), "+f"(c[1]), "+f"(c[2]), "+f"(c[3])
        : "r"(a[0]), "r"(a[1]), "r"(a[2]), "r"(a[3]), "r"(b[0]), "r"(b[1]));
}
__device__ __forceinline__ void cp_async16(uint32_t dst, const void* src) {
    asm volatile("cp.async.cg.shared.global [%0], [%1], 16;\n"
                 :: "r"(dst), "l"(src));
}
#define CP_COMMIT() asm volatile("cp.async.commit_group;\n" ::: "memory")
#define CP_WAIT(N)  asm volatile("cp.async.wait_group %0;\n" :: "n"(N) : "memory")
#define LDSM_X4(r0, r1, r2, r3, addr) \
    asm volatile("ldmatrix.sync.aligned.m8n8.x4.shared.b16 {%0,%1,%2,%3}, [%4];" \
                 : "=r"(r0), "=r"(r1), "=r"(r2), "=r"(r3) : "r"(addr))

// ---------------- fused weight pre-round (1 launch, 6 tensors) ------------
__global__ void round6_kernel(
    const float* s0, const float* s1, const float* s2, const float* s3,
    const float* s4, const float* s5,
    float* d0, float* d1, float* d2, float* d3, float* d4, float* d5,
    int nDD, int nDF) {
    int i = blockIdx.x * blockDim.x + threadIdx.x;
    const float* s; float* d; int n;
    switch (blockIdx.y) {
        case 0: s = s0; d = d0; n = nDD; break;
        case 1: s = s1; d = d1; n = nDD; break;
        case 2: s = s2; d = d2; n = nDD; break;
        case 3: s = s3; d = d3; n = nDD; break;
        case 4: s = s4; d = d4; n = nDF; break;
        default: s = s5; d = d5; n = nDF; break;
    }
    if (i >= n) return;
    float4 v = ((const float4*)s)[i];
    v.x = rnd32(v.x); v.y = rnd32(v.y); v.z = rnd32(v.z); v.w = rnd32(v.w);
    ((float4*)d)[i] = v;
}

// ---------------- embedding + PE ----------------
__global__ void embed_kernel(const int* __restrict__ x,
                             const float* __restrict__ emb,
                             float* __restrict__ h, float* __restrict__ hr) {
    int idx = blockIdx.x * blockDim.x + threadIdx.x;
    int row = idx >> 10, d = idx & (D_ - 1);
    int tok = x[row], s = row & (S_ - 1);
    float val = emb[(size_t)tok * D_ + d] * 32.0f;
    float div = expf((float)(d & ~1) * (-0.00899447301960227f));
    float ang = (float)s * div;
    float v = val + ((d & 1) ? cosf(ang) : sinf(ang));
    h[idx]  = v;
    hr[idx] = rnd32(v);
}

// ---------------- pipelined tf32 GEMM (R11 proven config) -----------------
// 128x128 tile, 256 thr = 8 warps (2x4), warp 64x32, 3 stages, 2 CTAs/SM.
constexpr int STAGES  = 3;
constexpr int ALD     = 36;
constexpr int BLD     = 136;
constexpr int A_STAGE = 128 * ALD;
constexpr int B_STAGE = 32 * BLD;
constexpr int STAGE_F = A_STAGE + B_STAGE;
constexpr int GEMM_SMEM_BYTES = STAGES * STAGE_F * 4;

template<int RELU, int ROUND>
__device__ __forceinline__ void gemm_body(
    const float* __restrict__ A, const float* __restrict__ W,
    const float* __restrict__ bias, float* __restrict__ C, int N, int K) {
    extern __shared__ float smf[];
    const uint32_t smem_base = (uint32_t)__cvta_generic_to_shared(smf);

    const int t    = threadIdx.x;
    const int m0   = blockIdx.y * 128;
    const int n0   = blockIdx.x * 128;
    const int warp = t >> 5, lane = t & 31;
    const int wm   = warp >> 2, wn = warp & 3;
    const int g    = lane >> 2, tg = lane & 3;
    const int li   = lane & 7, sel = lane >> 3;

    const int aR  = t >> 3;
    const int aK4 = (t & 7) << 2;
    const int bK  = t >> 5;
    const int bN4 = (t & 31) << 2;

    const float* Ag = A + (size_t)m0 * K;
    const float* Bg = W + n0;

    float acc[4][4][4];
    #pragma unroll
    for (int i = 0; i < 4; i++)
        #pragma unroll
        for (int j = 0; j < 4; j++)
            #pragma unroll
            for (int r = 0; r < 4; r++) acc[i][j][r] = 0.0f;

    auto prefetch = [&](int kt, int stage) {
        const int k0 = kt << 5;
        uint32_t As = smem_base + (stage * STAGE_F) * 4;
        uint32_t Bs = As + A_STAGE * 4;
        #pragma unroll
        for (int i = 0; i < 4; i++) {
            int r = aR + i * 32;
            cp_async16(As + (r * ALD + aK4) * 4, Ag + (size_t)r * K + k0 + aK4);
        }
        #pragma unroll
        for (int i = 0; i < 4; i++) {
            int kk = bK + i * 8;
            cp_async16(Bs + (kk * BLD + bN4) * 4,
                       Bg + (size_t)(k0 + kk) * N + bN4);
        }
    };

    const int ldsmRow = wm * 64 + li + 8 * (sel & 1);
    const int ldsmCol = 4 * (sel >> 1);

    auto compute = [&](int stage) {
        const uint32_t As_u = smem_base + (stage * STAGE_F) * 4;
        const uint32_t* Bs = (const uint32_t*)(smf + stage * STAGE_F) + A_STAGE;
        uint32_t aBase[4];
        #pragma unroll
        for (int mf = 0; mf < 4; mf++)
            aBase[mf] = As_u + ((ldsmRow + mf * 16) * ALD + ldsmCol) * 4;
        #pragma unroll
        for (int ks = 0; ks < 4; ks++) {
            const int k8 = ks << 3;
            uint32_t a[4][4], b[4][2];
            #pragma unroll
            for (int mf = 0; mf < 4; mf++)
                LDSM_X4(a[mf][0], a[mf][1], a[mf][2], a[mf][3],
                        aBase[mf] + k8 * 4);
            #pragma unroll
            for (int nf = 0; nf < 4; nf++) {
                const int nb = wn * 32 + nf * 8 + g;
                b[nf][0] = Bs[(k8 + tg)     * BLD + nb];
                b[nf][1] = Bs[(k8 + tg + 4) * BLD + nb];
            }
            #pragma unroll
            for (int mf = 0; mf < 4; mf++)
                #pragma unroll
                for (int nf = 0; nf < 4; nf++)
                    mma_tf32(acc[mf][nf], a[mf], b[nf]);
        }
    };

    const int nk = K >> 5;
    prefetch(0, 0); CP_COMMIT();
    prefetch(1, 1); CP_COMMIT();

    int st = 0, pf = 2;
    for (int kt = 0; kt < nk; kt++) {
        CP_WAIT(1);
        __syncthreads();
        if (kt + 2 < nk) prefetch(kt + 2, pf);
        CP_COMMIT();
        compute(st);
        st = (st == 2) ? 0 : st + 1;
        pf = (pf == 2) ? 0 : pf + 1;
    }

    #pragma unroll
    for (int mf = 0; mf < 4; mf++) {
        int r0 = m0 + wm * 64 + mf * 16 + g;
        int r1 = r0 + 8;
        #pragma unroll
        for (int nf = 0; nf < 4; nf++) {
            int col = n0 + wn * 32 + nf * 8 + tg * 2;
            float2 bb = *(const float2*)&bias[col];
            float2 o0, o1;
            o0.x = acc[mf][nf][0] + bb.x;
            o0.y = acc[mf][nf][1] + bb.y;
            o1.x = acc[mf][nf][2] + bb.x;
            o1.y = acc[mf][nf][3] + bb.y;
            if (RELU) {
                o0.x = fmaxf(o0.x, 0.f); o0.y = fmaxf(o0.y, 0.f);
                o1.x = fmaxf(o1.x, 0.f); o1.y = fmaxf(o1.y, 0.f);
            }
            if (ROUND) {
                o0.x = rnd32(o0.x); o0.y = rnd32(o0.y);
                o1.x = rnd32(o1.x); o1.y = rnd32(o1.y);
            }
            *(float2*)&C[(size_t)r0 * N + col] = o0;
            *(float2*)&C[(size_t)r1 * N + col] = o1;
        }
    }
}

template<int RELU, int ROUND>
__global__ __launch_bounds__(256, 2) void gemm_tf32(
    const float* __restrict__ A, const float* __restrict__ W,
    const float* __restrict__ bias, float* __restrict__ C, int N, int K) {
    gemm_body<RELU, ROUND>(A, W, bias, C, N, K);
}

__global__ __launch_bounds__(256, 2) void gemm_qkv(
    const float* __restrict__ A,
    const float* __restrict__ wq, const float* __restrict__ bq,
    const float* __restrict__ wk, const float* __restrict__ bk,
    const float* __restrict__ wv, const float* __restrict__ bv,
    float* __restrict__ oq, float* __restrict__ ok, float* __restrict__ ov) {
    const float* W; const float* bias; float* C;
    if (blockIdx.z == 0)      { W = wq; bias = bq; C = oq; }
    else if (blockIdx.z == 1) { W = wk; bias = bk; C = ok; }
    else                      { W = wv; bias = bv; C = ov; }
    gemm_body<0, 1>(A, W, bias, C, D_, D_);
}

// ---------------- flash attention (R11 + early prefetch via P-staging) ----
constexpr int AKLD = 68, AVLD = 72, APLD = 68;
constexpr int TN_   = 64;
constexpr int AK_BUF = TN_ * AKLD;
constexpr int AV_BUF = TN_ * AVLD;
constexpr int ATTN_SMEM =
    (2 * AK_BUF + 2 * AV_BUF + 128 * APLD) * 4 + S_;

__global__ __launch_bounds__(256, 2) void attn_mma(
    const float* __restrict__ Q, const float* __restrict__ K,
    const float* __restrict__ V, const int* __restrict__ mask,
    float* __restrict__ ctx) {
    extern __shared__ float smf[];
    float*    Ksf = smf;
    float*    Vsf = smf + 2 * AK_BUF;
    uint32_t* Ps  = (uint32_t*)(Vsf + 2 * AV_BUF);
    char*     msk = (char*)(Ps + 128 * APLD);
    const uint32_t sb   = (uint32_t)__cvta_generic_to_shared(smf);
    const uint32_t sbV  = sb + 2 * AK_BUF * 4;
    const uint32_t sbP  = sbV + 2 * AV_BUF * 4;

    const int qt = blockIdx.x, h = blockIdx.y, b = blockIdx.z;
    const int t = threadIdx.x, w = t >> 5, lane = t & 31;
    const int g = lane >> 2, tg = lane & 3;
    const int li = lane & 7, sel = lane >> 3;
    const int r0 = w * 16 + g, r1 = r0 + 8;

    auto prefetch = [&](int kt, int buf) {
        const uint32_t kb = sb  + buf * AK_BUF * 4;
        const uint32_t vb = sbV + buf * AV_BUF * 4;
        #pragma unroll
        for (int i = 0; i < 4; i++) {
            int chunk = t + i * 256;
            int r = chunk >> 4, c4 = (chunk & 15) << 2;
            size_t gofs = (size_t)(b * S_ + kt * TN_ + r) * D_ + h * 64 + c4;
            cp_async16(kb + (r * AKLD + c4) * 4, K + gofs);
            cp_async16(vb + (r * AVLD + c4) * 4, V + gofs);
        }
    };

    // issue first K/V prefetches immediately; Q stages through P buffer
    prefetch(0, 0); CP_COMMIT();
    prefetch(1, 1); CP_COMMIT();

    for (int i = t; i < S_; i += 256) msk[i] = (char)mask[b * S_ + i];
    for (int i = t; i < 128 * 16; i += 256) {
        int r = i >> 4, c4 = (i & 15) << 2;
        float4 qv = *(const float4*)&Q[(size_t)(b * S_ + qt * 128 + r) * D_ +
                                       h * 64 + c4];
        uint32_t* dst = &Ps[r * APLD + c4];
        dst[0] = __float_as_uint(qv.x); dst[1] = __float_as_uint(qv.y);
        dst[2] = __float_as_uint(qv.z); dst[3] = __float_as_uint(qv.w);
    }
    __syncthreads();
    uint32_t qr[8][4];
    #pragma unroll
    for (int kb8 = 0; kb8 < 8; kb8++) {
        int kb = kb8 * 8;
        qr[kb8][0] = Ps[r0 * APLD + kb + tg];
        qr[kb8][1] = Ps[r1 * APLD + kb + tg];
        qr[kb8][2] = Ps[r0 * APLD + kb + tg + 4];
        qr[kb8][3] = Ps[r1 * APLD + kb + tg + 4];
    }
    // no extra barrier: mainloop's first __syncthreads (below) orders
    // Q reg-loads before any P writes.

    float m_i[2] = {-INFINITY, -INFINITY}, l_i[2] = {0.f, 0.f};
    float o[8][4];
    #pragma unroll
    for (int nf = 0; nf < 8; nf++)
        #pragma unroll
        for (int r = 0; r < 4; r++) o[nf][r] = 0.f;

    const uint32_t pBase =
        sbP + ((w * 16 + li + 8 * (sel & 1)) * APLD + 4 * (sel >> 1)) * 4;

    const int NT = S_ / TN_;
    for (int kt = 0; kt < NT; kt++) {
        CP_WAIT(1);
        __syncthreads();
        const uint32_t* Kc = (const uint32_t*)(Ksf + (kt & 1) * AK_BUF);
        const uint32_t* Vc = (const uint32_t*)(Vsf + (kt & 1) * AV_BUF);

        float s[8][4];
        #pragma unroll
        for (int nf = 0; nf < 8; nf++)
            #pragma unroll
            for (int r = 0; r < 4; r++) s[nf][r] = 0.f;
        #pragma unroll
        for (int kb8 = 0; kb8 < 8; kb8++) {
            int kb = kb8 * 8;
            #pragma unroll
            for (int nf = 0; nf < 8; nf++) {
                uint32_t bf[2];
                bf[0] = Kc[(nf * 8 + g) * AKLD + kb + tg];
                bf[1] = Kc[(nf * 8 + g) * AKLD + kb + tg + 4];
                mma_tf32(s[nf], qr[kb8], bf);
            }
        }

        float mx0 = -INFINITY, mx1 = -INFINITY;
        #pragma unroll
        for (int nf = 0; nf < 8; nf++) {
            int c = kt * TN_ + nf * 8 + 2 * tg;
            s[nf][0] *= 0.125f; s[nf][1] *= 0.125f;
            s[nf][2] *= 0.125f; s[nf][3] *= 0.125f;
            if (msk[c] == 0)     { s[nf][0] = -1e9f; s[nf][2] = -1e9f; }
            if (msk[c + 1] == 0) { s[nf][1] = -1e9f; s[nf][3] = -1e9f; }
            mx0 = fmaxf(mx0, fmaxf(s[nf][0], s[nf][1]));
            mx1 = fmaxf(mx1, fmaxf(s[nf][2], s[nf][3]));
        }
        #pragma unroll
        for (int off = 1; off <= 2; off <<= 1) {
            mx0 = fmaxf(mx0, __shfl_xor_sync(0xffffffffu, mx0, off));
            mx1 = fmaxf(mx1, __shfl_xor_sync(0xffffffffu, mx1, off));
        }
        float mn0 = fmaxf(m_i[0], mx0), mn1 = fmaxf(m_i[1], mx1);
        float corr0 = __expf(m_i[0] - mn0), corr1 = __expf(m_i[1] - mn1);
        m_i[0] = mn0; m_i[1] = mn1;

        float rs0 = 0.f, rs1 = 0.f;
        #pragma unroll
        for (int nf = 0; nf < 8; nf++) {
            float p0 = __expf(s[nf][0] - mn0), p1 = __expf(s[nf][1] - mn0);
            float p2 = __expf(s[nf][2] - mn1), p3 = __expf(s[nf][3] - mn1);
            rs0 += p0 + p1; rs1 += p2 + p3;
            *(uint2*)&Ps[r0 * APLD + nf * 8 + 2 * tg] =
                make_uint2(f2tf32(p0), f2tf32(p1));
            *(uint2*)&Ps[r1 * APLD + nf * 8 + 2 * tg] =
                make_uint2(f2tf32(p2), f2tf32(p3));
        }
        #pragma unroll
        for (int off = 1; off <= 2; off <<= 1) {
            rs0 += __shfl_xor_sync(0xffffffffu, rs0, off);
            rs1 += __shfl_xor_sync(0xffffffffu, rs1, off);
        }
        l_i[0] = l_i[0] * corr0 + rs0;
        l_i[1] = l_i[1] * corr1 + rs1;
        #pragma unroll
        for (int nf = 0; nf < 8; nf++) {
            o[nf][0] *= corr0; o[nf][1] *= corr0;
            o[nf][2] *= corr1; o[nf][3] *= corr1;
        }
        __syncwarp();

        #pragma unroll
        for (int kb = 0; kb < TN_; kb += 8) {
            uint32_t a[4];
            LDSM_X4(a[0], a[1], a[2], a[3], pBase + kb * 4);
            #pragma unroll
            for (int nf = 0; nf < 8; nf++) {
                uint32_t bf[2];
                bf[0] = Vc[(kb + tg) * AVLD + nf * 8 + g];
                bf[1] = Vc[(kb + tg + 4) * AVLD + nf * 8 + g];
                mma_tf32(o[nf], a, bf);
            }
        }
        __syncthreads();
        if (kt + 2 < NT) prefetch(kt + 2, kt & 1);
        CP_COMMIT();
    }

    float inv0 = 1.f / l_i[0], inv1 = 1.f / l_i[1];
    size_t row0 = (size_t)(b * S_ + qt * 128 + r0) * D_ + h * 64;
    size_t row1 = (size_t)(b * S_ + qt * 128 + r1) * D_ + h * 64;
    #pragma unroll
    for (int nf = 0; nf < 8; nf++) {
        int col = nf * 8 + 2 * tg;
        *(float2*)&ctx[row0 + col] =
            make_float2(rnd32(o[nf][0] * inv0), rnd32(o[nf][1] * inv0));
        *(float2*)&ctx[row1 + col] =
            make_float2(rnd32(o[nf][2] * inv1), rnd32(o[nf][3] * inv1));
    }
}

// ---------------- fused residual + LayerNorm (2 rows / block) -------------
template<int WR>
__global__ __launch_bounds__(512) void ln_kernel(
    const float* __restrict__ a, const float* __restrict__ r,
    const float* __restrict__ g, const float* __restrict__ be,
    float* __restrict__ out, float* __restrict__ outr) {
    const int t   = threadIdx.x;
    const int sub = t >> 8;            // 0/1 -> which row
    const int tt  = t & 255;
    const int row = blockIdx.x * 2 + sub;

    float4 x = ((const float4*)a)[(size_t)row * 256 + tt];
    if (r) {
        float4 y = ((const float4*)r)[(size_t)row * 256 + tt];
        x.x += y.x; x.y += y.y; x.z += y.z; x.w += y.w;
    }
    float s  = x.x + x.y + x.z + x.w;
    float ss = x.x*x.x + x.y*x.y + x.z*x.z + x.w*x.w;
    #pragma unroll
    for (int off = 16; off; off >>= 1) {
        s  += __shfl_xor_sync(0xffffffffu, s,  off);
        ss += __shfl_xor_sync(0xffffffffu, ss, off);
    }
    __shared__ float wsum[16], wsq[16];
    int warp = t >> 5, lane = t & 31;
    if (lane == 0) { wsum[warp] = s; wsq[warp] = ss; }
    __syncthreads();
    s = 0.f; ss = 0.f;
    #pragma unroll
    for (int i = 0; i < 8; i++) {
        s  += wsum[sub * 8 + i];
        ss += wsq [sub * 8 + i];
    }
    float mean = s * (1.f/1024.f);
    float var  = ss * (1.f/1024.f) - mean*mean;
    float rstd = rsqrtf(var + 1e-5f);
    float4 gg = ((const float4*)g)[tt];
    float4 bb = ((const float4*)be)[tt];
    float4 o;
    o.x = (x.x - mean)*rstd*gg.x + bb.x;
    o.y = (x.y - mean)*rstd*gg.y + bb.y;
    o.z = (x.z - mean)*rstd*gg.z + bb.z;
    o.w = (x.w - mean)*rstd*gg.w + bb.w;
    ((float4*)out)[(size_t)row * 256 + tt] = o;
    if (WR) {
        float4 q;
        q.x = rnd32(o.x); q.y = rnd32(o.y); q.z = rnd32(o.z); q.w = rnd32(o.w);
        ((float4*)outr)[(size_t)row * 256 + tt] = q;
    }
}

// ---------------- launch ----------------
extern "C" void kernel_launch(void* const* d_in, const int* in_sizes, int n_in,
                              void* d_out, int out_size) {
    (void)in_sizes; (void)n_in; (void)out_size;
    const int*   x    = (const int*)  d_in[0];
    const int*   mask = (const int*)  d_in[1];
    const float* emb  = (const float*)d_in[2];
    const float* wq   = (const float*)d_in[3];
    const float* bq   = (const float*)d_in[4];
    const float* wk   = (const float*)d_in[5];
    const float* bk   = (const float*)d_in[6];
    const float* wv   = (const float*)d_in[7];
    const float* bv   = (const float*)d_in[8];
    const float* wo   = (const float*)d_in[9];
    const float* bo   = (const float*)d_in[10];
    const float* w1   = (const float*)d_in[11];
    const float* b1   = (const float*)d_in[12];
    const float* w2   = (const float*)d_in[13];
    const float* b2   = (const float*)d_in[14];
    const float* g1   = (const float*)d_in[15];
    const float* be1  = (const float*)d_in[16];
    const float* g2   = (const float*)d_in[17];
    const float* be2  = (const float*)d_in[18];
    const float* gf   = (const float*)d_in[19];
    const float* bf   = (const float*)d_in[20];
    float* out = (float*)d_out;

    float *gh, *ghr, *gq, *gk, *gv, *gctx, *gp, *gff;
    float *cwq, *cwk, *cwv, *cwo, *cw1, *cw2;
    cudaGetSymbolAddress((void**)&gh,   g_h);
    cudaGetSymbolAddress((void**)&ghr,  g_hr);
    cudaGetSymbolAddress((void**)&gq,   g_q);
    cudaGetSymbolAddress((void**)&gk,   g_k);
    cudaGetSymbolAddress((void**)&gv,   g_v);
    cudaGetSymbolAddress((void**)&gctx, g_ctx);
    cudaGetSymbolAddress((void**)&gp,   g_p);
    cudaGetSymbolAddress((void**)&gff,  g_ff);
    cudaGetSymbolAddress((void**)&cwq,  g_cwq);
    cudaGetSymbolAddress((void**)&cwk,  g_cwk);
    cudaGetSymbolAddress((void**)&cwv,  g_cwv);
    cudaGetSymbolAddress((void**)&cwo,  g_cwo);
    cudaGetSymbolAddress((void**)&cw1,  g_cw1);
    cudaGetSymbolAddress((void**)&cw2,  g_cw2);

    cudaFuncSetAttribute(attn_mma,
        cudaFuncAttributeMaxDynamicSharedMemorySize, ATTN_SMEM);
    cudaFuncSetAttribute(gemm_tf32<0,0>,
        cudaFuncAttributeMaxDynamicSharedMemorySize, GEMM_SMEM_BYTES);
    cudaFuncSetAttribute(gemm_tf32<0,1>,
        cudaFuncAttributeMaxDynamicSharedMemorySize, GEMM_SMEM_BYTES);
    cudaFuncSetAttribute(gemm_tf32<1,1>,
        cudaFuncAttributeMaxDynamicSharedMemorySize, GEMM_SMEM_BYTES);
    cudaFuncSetAttribute(gemm_qkv,
        cudaFuncAttributeMaxDynamicSharedMemorySize, GEMM_SMEM_BYTES);

    const int nDD = L_ * D_ * D_ / 4, nDF = L_ * D_ * DFF_ / 4;
    round6_kernel<<<dim3((nDF + 255) / 256, 6), 256>>>(
        wq, wk, wv, wo, w1, w2, cwq, cwk, cwv, cwo, cw1, cw2, nDD, nDF);

    embed_kernel<<<(BS_ * D_) / 256, 256>>>(x, emb, gh, ghr);

    for (int l = 0; l < L_; l++) {
        const size_t wOff = (size_t)l * D_ * D_;
        const size_t fOff = (size_t)l * D_ * DFF_;
        gemm_qkv<<<dim3(8, 64, 3), 256, GEMM_SMEM_BYTES>>>(
            ghr, cwq + wOff, bq + l * D_, cwk + wOff, bk + l * D_,
            cwv + wOff, bv + l * D_, gq, gk, gv);
        attn_mma<<<dim3(S_ / 128, H_, B_), 256, ATTN_SMEM>>>(
            gq, gk, gv, mask, gctx);
        gemm_tf32<0,0><<<dim3(8, 64), 256, GEMM_SMEM_BYTES>>>(
            gctx, cwo + wOff, bo + l * D_, gp, D_, D_);
        ln_kernel<1><<<BS_ / 2, 512>>>(gh, gp, g1 + l * D_, be1 + l * D_,
                                       gh, ghr);
        gemm_tf32<1,1><<<dim3(32, 64), 256, GEMM_SMEM_BYTES>>>(
            ghr, cw1 + fOff, b1 + l * DFF_, gff, DFF_, D_);
        gemm_tf32<0,0><<<dim3(8, 64), 256, GEMM_SMEM_BYTES>>>(
            gff, cw2 + fOff, b2 + l * D_, gp, D_, DFF_);
        ln_kernel<1><<<BS_ / 2, 512>>>(gh, gp, g2 + l * D_, be2 + l * D_,
                                       gh, ghr);
    }
    ln_kernel<0><<<BS_ / 2, 512>>>(gh, nullptr, gf, bf, out, nullptr);
}

// round 17
// speedup vs baseline: 1.2027x; 1.0133x over previous
#include <cuda_runtime.h>
#include <math.h>
#include <stdint.h>

constexpr int B_=4, S_=2048, D_=1024, H_=16, DFF_=4096, L_=6;
constexpr int BS_ = B_*S_;

// ---------------- scratch ----------------
__device__ float g_h  [(size_t)BS_*D_];
__device__ float g_hr [(size_t)BS_*D_];
__device__ float g_q  [(size_t)BS_*D_];
__device__ float g_k  [(size_t)BS_*D_];
__device__ float g_v  [(size_t)BS_*D_];
__device__ float g_ctx[(size_t)BS_*D_];
__device__ float g_p  [(size_t)BS_*D_];
__device__ float g_ff [(size_t)BS_*DFF_];
__device__ float g_cwq[(size_t)L_*D_*D_];
__device__ float g_cwk[(size_t)L_*D_*D_];
__device__ float g_cwv[(size_t)L_*D_*D_];
__device__ float g_cwo[(size_t)L_*D_*D_];
__device__ float g_cw1[(size_t)L_*D_*DFF_];
__device__ float g_cw2[(size_t)L_*DFF_*D_];

// ---------------- helpers ----------------
__device__ __forceinline__ uint32_t f2tf32(float x) {
    uint32_t r; asm("cvt.rna.tf32.f32 %0, %1;" : "=r"(r) : "f"(x)); return r;
}
__device__ __forceinline__ float rnd32(float x) {
    return __uint_as_float(f2tf32(x));
}
__device__ __forceinline__ void mma_tf32(float* c, const uint32_t* a,
                                         const uint32_t* b) {
    asm volatile(
        "mma.sync.aligned.m16n8k8.row.col.f32.tf32.tf32.f32 "
        "{%0,%1,%2,%3}, {%4,%5,%6,%7}, {%8,%9}, {%0,%1,%2,%3};\n"
        : "+f"(c[0]), "+f"(c[1]), "+f"(c[2]), "+f"(c[3])
        : "r"(a[0]), "r"(a[1]), "r"(a[2]), "r"(a[3]), "r"(b[0]), "r"(b[1]));
}
__device__ __forceinline__ void cp_async16(uint32_t dst, const void* src) {
    asm volatile("cp.async.cg.shared.global [%0], [%1], 16;\n"
                 :: "r"(dst), "l"(src));
}
#define CP_COMMIT() asm volatile("cp.async.commit_group;\n" ::: "memory")
#define CP_WAIT(N)  asm volatile("cp.async.wait_group %0;\n" :: "n"(N) : "memory")
#define LDSM_X4(r0, r1, r2, r3, addr) \
    asm volatile("ldmatrix.sync.aligned.m8n8.x4.shared.b16 {%0,%1,%2,%3}, [%4];" \
                 : "=r"(r0), "=r"(r1), "=r"(r2), "=r"(r3) : "r"(addr))

// ---------------- fused weight pre-round (1 launch, 6 tensors) ------------
__global__ void round6_kernel(
    const float* s0, const float* s1, const float* s2, const float* s3,
    const float* s4, const float* s5,
    float* d0, float* d1, float* d2, float* d3, float* d4, float* d5,
    int nDD, int nDF) {
    int i = blockIdx.x * blockDim.x + threadIdx.x;
    const float* s; float* d; int n;
    switch (blockIdx.y) {
        case 0: s = s0; d = d0; n = nDD; break;
        case 1: s = s1; d = d1; n = nDD; break;
        case 2: s = s2; d = d2; n = nDD; break;
        case 3: s = s3; d = d3; n = nDD; break;
        case 4: s = s4; d = d4; n = nDF; break;
        default: s = s5; d = d5; n = nDF; break;
    }
    if (i >= n) return;
    float4 v = ((const float4*)s)[i];
    v.x = rnd32(v.x); v.y = rnd32(v.y); v.z = rnd32(v.z); v.w = rnd32(v.w);
    ((float4*)d)[i] = v;
}

// ---------------- embedding + PE ----------------
__global__ void embed_kernel(const int* __restrict__ x,
                             const float* __restrict__ emb,
                             float* __restrict__ h, float* __restrict__ hr) {
    int idx = blockIdx.x * blockDim.x + threadIdx.x;
    int row = idx >> 10, d = idx & (D_ - 1);
    int tok = x[row], s = row & (S_ - 1);
    float val = emb[(size_t)tok * D_ + d] * 32.0f;
    float div = expf((float)(d & ~1) * (-0.00899447301960227f));
    float ang = (float)s * div;
    float v = val + ((d & 1) ? cosf(ang) : sinf(ang));
    h[idx]  = v;
    hr[idx] = rnd32(v);
}

// ---------------- pipelined tf32 GEMM (R11 proven config) -----------------
constexpr int STAGES  = 3;
constexpr int ALD     = 36;
constexpr int BLD     = 136;
constexpr int A_STAGE = 128 * ALD;
constexpr int B_STAGE = 32 * BLD;
constexpr int STAGE_F = A_STAGE + B_STAGE;
constexpr int GEMM_SMEM_BYTES = STAGES * STAGE_F * 4;

template<int RELU, int ROUND>
__device__ __forceinline__ void gemm_body(
    const float* __restrict__ A, const float* __restrict__ W,
    const float* __restrict__ bias, float* __restrict__ C, int N, int K) {
    extern __shared__ float smf[];
    const uint32_t smem_base = (uint32_t)__cvta_generic_to_shared(smf);

    const int t    = threadIdx.x;
    const int m0   = blockIdx.y * 128;
    const int n0   = blockIdx.x * 128;
    const int warp = t >> 5, lane = t & 31;
    const int wm   = warp >> 2, wn = warp & 3;
    const int g    = lane >> 2, tg = lane & 3;
    const int li   = lane & 7, sel = lane >> 3;

    const int aR  = t >> 3;
    const int aK4 = (t & 7) << 2;
    const int bK  = t >> 5;
    const int bN4 = (t & 31) << 2;

    const float* Ag = A + (size_t)m0 * K;
    const float* Bg = W + n0;

    float acc[4][4][4];
    #pragma unroll
    for (int i = 0; i < 4; i++)
        #pragma unroll
        for (int j = 0; j < 4; j++)
            #pragma unroll
            for (int r = 0; r < 4; r++) acc[i][j][r] = 0.0f;

    auto prefetch = [&](int kt, int stage) {
        const int k0 = kt << 5;
        uint32_t As = smem_base + (stage * STAGE_F) * 4;
        uint32_t Bs = As + A_STAGE * 4;
        #pragma unroll
        for (int i = 0; i < 4; i++) {
            int r = aR + i * 32;
            cp_async16(As + (r * ALD + aK4) * 4, Ag + (size_t)r * K + k0 + aK4);
        }
        #pragma unroll
        for (int i = 0; i < 4; i++) {
            int kk = bK + i * 8;
            cp_async16(Bs + (kk * BLD + bN4) * 4,
                       Bg + (size_t)(k0 + kk) * N + bN4);
        }
    };

    const int ldsmRow = wm * 64 + li + 8 * (sel & 1);
    const int ldsmCol = 4 * (sel >> 1);

    auto compute = [&](int stage) {
        const uint32_t As_u = smem_base + (stage * STAGE_F) * 4;
        const uint32_t* Bs = (const uint32_t*)(smf + stage * STAGE_F) + A_STAGE;
        uint32_t aBase[4];
        #pragma unroll
        for (int mf = 0; mf < 4; mf++)
            aBase[mf] = As_u + ((ldsmRow + mf * 16) * ALD + ldsmCol) * 4;
        #pragma unroll
        for (int ks = 0; ks < 4; ks++) {
            const int k8 = ks << 3;
            uint32_t a[4][4], b[4][2];
            #pragma unroll
            for (int mf = 0; mf < 4; mf++)
                LDSM_X4(a[mf][0], a[mf][1], a[mf][2], a[mf][3],
                        aBase[mf] + k8 * 4);
            #pragma unroll
            for (int nf = 0; nf < 4; nf++) {
                const int nb = wn * 32 + nf * 8 + g;
                b[nf][0] = Bs[(k8 + tg)     * BLD + nb];
                b[nf][1] = Bs[(k8 + tg + 4) * BLD + nb];
            }
            #pragma unroll
            for (int mf = 0; mf < 4; mf++)
                #pragma unroll
                for (int nf = 0; nf < 4; nf++)
                    mma_tf32(acc[mf][nf], a[mf], b[nf]);
        }
    };

    const int nk = K >> 5;
    prefetch(0, 0); CP_COMMIT();
    prefetch(1, 1); CP_COMMIT();

    int st = 0, pf = 2;
    for (int kt = 0; kt < nk; kt++) {
        CP_WAIT(1);
        __syncthreads();
        if (kt + 2 < nk) prefetch(kt + 2, pf);
        CP_COMMIT();
        compute(st);
        st = (st == 2) ? 0 : st + 1;
        pf = (pf == 2) ? 0 : pf + 1;
    }

    #pragma unroll
    for (int mf = 0; mf < 4; mf++) {
        int r0 = m0 + wm * 64 + mf * 16 + g;
        int r1 = r0 + 8;
        #pragma unroll
        for (int nf = 0; nf < 4; nf++) {
            int col = n0 + wn * 32 + nf * 8 + tg * 2;
            float2 bb = *(const float2*)&bias[col];
            float2 o0, o1;
            o0.x = acc[mf][nf][0] + bb.x;
            o0.y = acc[mf][nf][1] + bb.y;
            o1.x = acc[mf][nf][2] + bb.x;
            o1.y = acc[mf][nf][3] + bb.y;
            if (RELU) {
                o0.x = fmaxf(o0.x, 0.f); o0.y = fmaxf(o0.y, 0.f);
                o1.x = fmaxf(o1.x, 0.f); o1.y = fmaxf(o1.y, 0.f);
            }
            if (ROUND) {
                o0.x = rnd32(o0.x); o0.y = rnd32(o0.y);
                o1.x = rnd32(o1.x); o1.y = rnd32(o1.y);
            }
            *(float2*)&C[(size_t)r0 * N + col] = o0;
            *(float2*)&C[(size_t)r1 * N + col] = o1;
        }
    }
}

template<int RELU, int ROUND>
__global__ __launch_bounds__(256, 2) void gemm_tf32(
    const float* __restrict__ A, const float* __restrict__ W,
    const float* __restrict__ bias, float* __restrict__ C, int N, int K) {
    gemm_body<RELU, ROUND>(A, W, bias, C, N, K);
}

__global__ __launch_bounds__(256, 2) void gemm_qkv(
    const float* __restrict__ A,
    const float* __restrict__ wq, const float* __restrict__ bq,
    const float* __restrict__ wk, const float* __restrict__ bk,
    const float* __restrict__ wv, const float* __restrict__ bv,
    float* __restrict__ oq, float* __restrict__ ok, float* __restrict__ ov) {
    const float* W; const float* bias; float* C;
    if (blockIdx.z == 0)      { W = wq; bias = bq; C = oq; }
    else if (blockIdx.z == 1) { W = wk; bias = bk; C = ok; }
    else                      { W = wv; bias = bv; C = ov; }
    gemm_body<0, 1>(A, W, bias, C, D_, D_);
}

// ---------------- flash attention: LDSM K-frags, prescaled Q --------------
constexpr int AKLD = 68, AVLD = 72, APLD = 68;
constexpr int TN_   = 64;
constexpr int AK_BUF = TN_ * AKLD;
constexpr int AV_BUF = TN_ * AVLD;
constexpr int ATTN_SMEM =
    (2 * AK_BUF + 2 * AV_BUF + 128 * APLD) * 4 + S_;

__global__ __launch_bounds__(256, 2) void attn_mma(
    const float* __restrict__ Q, const float* __restrict__ K,
    const float* __restrict__ V, const int* __restrict__ mask,
    float* __restrict__ ctx) {
    extern __shared__ float smf[];
    float*    Ksf = smf;
    float*    Vsf = smf + 2 * AK_BUF;
    uint32_t* Ps  = (uint32_t*)(Vsf + 2 * AV_BUF);
    char*     msk = (char*)(Ps + 128 * APLD);
    const uint32_t sb   = (uint32_t)__cvta_generic_to_shared(smf);
    const uint32_t sbV  = sb + 2 * AK_BUF * 4;
    const uint32_t sbP  = sbV + 2 * AV_BUF * 4;

    const int qt = blockIdx.x, h = blockIdx.y, b = blockIdx.z;
    const int t = threadIdx.x, w = t >> 5, lane = t & 31;
    const int g = lane >> 2, tg = lane & 3;
    const int li = lane & 7, sel = lane >> 3;
    const int r0 = w * 16 + g, r1 = r0 + 8;

    auto prefetch = [&](int kt, int buf) {
        const uint32_t kb = sb  + buf * AK_BUF * 4;
        const uint32_t vb = sbV + buf * AV_BUF * 4;
        #pragma unroll
        for (int i = 0; i < 4; i++) {
            int chunk = t + i * 256;
            int r = chunk >> 4, c4 = (chunk & 15) << 2;
            size_t gofs = (size_t)(b * S_ + kt * TN_ + r) * D_ + h * 64 + c4;
            cp_async16(kb + (r * AKLD + c4) * 4, K + gofs);
            cp_async16(vb + (r * AVLD + c4) * 4, V + gofs);
        }
    };

    prefetch(0, 0); CP_COMMIT();
    prefetch(1, 1); CP_COMMIT();

    for (int i = t; i < S_; i += 256) msk[i] = (char)mask[b * S_ + i];
    // stage Q (pre-scaled by 0.125 — exponent-only, stays tf32-exact)
    for (int i = t; i < 128 * 16; i += 256) {
        int r = i >> 4, c4 = (i & 15) << 2;
        float4 qv = *(const float4*)&Q[(size_t)(b * S_ + qt * 128 + r) * D_ +
                                       h * 64 + c4];
        uint32_t* dst = &Ps[r * APLD + c4];
        dst[0] = __float_as_uint(qv.x * 0.125f);
        dst[1] = __float_as_uint(qv.y * 0.125f);
        dst[2] = __float_as_uint(qv.z * 0.125f);
        dst[3] = __float_as_uint(qv.w * 0.125f);
    }
    __syncthreads();
    uint32_t qr[8][4];
    #pragma unroll
    for (int kb8 = 0; kb8 < 8; kb8++) {
        int kb = kb8 * 8;
        qr[kb8][0] = Ps[r0 * APLD + kb + tg];
        qr[kb8][1] = Ps[r1 * APLD + kb + tg];
        qr[kb8][2] = Ps[r0 * APLD + kb + tg + 4];
        qr[kb8][3] = Ps[r1 * APLD + kb + tg + 4];
    }

    float m_i[2] = {-INFINITY, -INFINITY}, l_i[2] = {0.f, 0.f};
    float o[8][4];
    #pragma unroll
    for (int nf = 0; nf < 8; nf++)
        #pragma unroll
        for (int r = 0; r < 4; r++) o[nf][r] = 0.f;

    const uint32_t pBase =
        sbP + ((w * 16 + li + 8 * (sel & 1)) * APLD + 4 * (sel >> 1)) * 4;
    // K-fragment LDSM per-thread offset: tiles (nfp2+sel>>1, kb + (sel&1)*4)
    const uint32_t kfOff =
        (((sel >> 1) * 8 + li) * AKLD + (sel & 1) * 4) * 4;   // bytes

    const int NT = S_ / TN_;
    for (int kt = 0; kt < NT; kt++) {
        CP_WAIT(1);
        __syncthreads();
        const uint32_t kcU = sb + (kt & 1) * AK_BUF * 4;
        const uint32_t* Vc = (const uint32_t*)(Vsf + (kt & 1) * AV_BUF);

        // ---- S = Qs K^T : 32 LDSM.x4 + 64 mma ----
        float s[8][4];
        #pragma unroll
        for (int nf = 0; nf < 8; nf++)
            #pragma unroll
            for (int r = 0; r < 4; r++) s[nf][r] = 0.f;
        #pragma unroll
        for (int kb8 = 0; kb8 < 8; kb8++) {
            const uint32_t kbOff = kb8 * 32;   // 8 floats
            #pragma unroll
            for (int nfp = 0; nfp < 4; nfp++) {
                uint32_t bf[4];
                LDSM_X4(bf[0], bf[1], bf[2], bf[3],
                        kcU + nfp * 16 * AKLD * 4 + kbOff + kfOff);
                mma_tf32(s[nfp * 2],     qr[kb8], &bf[0]);
                mma_tf32(s[nfp * 2 + 1], qr[kb8], &bf[2]);
            }
        }

        // ---- mask + row max (scores already scaled via Q) ----
        float mx0 = -INFINITY, mx1 = -INFINITY;
        #pragma unroll
        for (int nf = 0; nf < 8; nf++) {
            int c = kt * TN_ + nf * 8 + 2 * tg;
            if (msk[c] == 0)     { s[nf][0] = -1e9f; s[nf][2] = -1e9f; }
            if (msk[c + 1] == 0) { s[nf][1] = -1e9f; s[nf][3] = -1e9f; }
            mx0 = fmaxf(mx0, fmaxf(s[nf][0], s[nf][1]));
            mx1 = fmaxf(mx1, fmaxf(s[nf][2], s[nf][3]));
        }
        #pragma unroll
        for (int off = 1; off <= 2; off <<= 1) {
            mx0 = fmaxf(mx0, __shfl_xor_sync(0xffffffffu, mx0, off));
            mx1 = fmaxf(mx1, __shfl_xor_sync(0xffffffffu, mx1, off));
        }
        float mn0 = fmaxf(m_i[0], mx0), mn1 = fmaxf(m_i[1], mx1);
        float corr0 = __expf(m_i[0] - mn0), corr1 = __expf(m_i[1] - mn1);
        m_i[0] = mn0; m_i[1] = mn1;

        float rs0 = 0.f, rs1 = 0.f;
        #pragma unroll
        for (int nf = 0; nf < 8; nf++) {
            float p0 = __expf(s[nf][0] - mn0), p1 = __expf(s[nf][1] - mn0);
            float p2 = __expf(s[nf][2] - mn1), p3 = __expf(s[nf][3] - mn1);
            rs0 += p0 + p1; rs1 += p2 + p3;
            *(uint2*)&Ps[r0 * APLD + nf * 8 + 2 * tg] =
                make_uint2(f2tf32(p0), f2tf32(p1));
            *(uint2*)&Ps[r1 * APLD + nf * 8 + 2 * tg] =
                make_uint2(f2tf32(p2), f2tf32(p3));
        }
        #pragma unroll
        for (int off = 1; off <= 2; off <<= 1) {
            rs0 += __shfl_xor_sync(0xffffffffu, rs0, off);
            rs1 += __shfl_xor_sync(0xffffffffu, rs1, off);
        }
        l_i[0] = l_i[0] * corr0 + rs0;
        l_i[1] = l_i[1] * corr1 + rs1;
        #pragma unroll
        for (int nf = 0; nf < 8; nf++) {
            o[nf][0] *= corr0; o[nf][1] *= corr0;
            o[nf][2] *= corr1; o[nf][3] *= corr1;
        }
        __syncwarp();

        #pragma unroll
        for (int kb = 0; kb < TN_; kb += 8) {
            uint32_t a[4];
            LDSM_X4(a[0], a[1], a[2], a[3], pBase + kb * 4);
            #pragma unroll
            for (int nf = 0; nf < 8; nf++) {
                uint32_t bf[2];
                bf[0] = Vc[(kb + tg) * AVLD + nf * 8 + g];
                bf[1] = Vc[(kb + tg + 4) * AVLD + nf * 8 + g];
                mma_tf32(o[nf], a, bf);
            }
        }
        __syncthreads();
        if (kt + 2 < NT) prefetch(kt + 2, kt & 1);
        CP_COMMIT();
    }

    float inv0 = 1.f / l_i[0], inv1 = 1.f / l_i[1];
    size_t row0 = (size_t)(b * S_ + qt * 128 + r0) * D_ + h * 64;
    size_t row1 = (size_t)(b * S_ + qt * 128 + r1) * D_ + h * 64;
    #pragma unroll
    for (int nf = 0; nf < 8; nf++) {
        int col = nf * 8 + 2 * tg;
        *(float2*)&ctx[row0 + col] =
            make_float2(rnd32(o[nf][0] * inv0), rnd32(o[nf][1] * inv0));
        *(float2*)&ctx[row1 + col] =
            make_float2(rnd32(o[nf][2] * inv1), rnd32(o[nf][3] * inv1));
    }
}

// ---------------- fused residual + LayerNorm (2 rows / block) -------------
template<int WR>
__global__ __launch_bounds__(512) void ln_kernel(
    const float* __restrict__ a, const float* __restrict__ r,
    const float* __restrict__ g, const float* __restrict__ be,
    float* __restrict__ out, float* __restrict__ outr) {
    const int t   = threadIdx.x;
    const int sub = t >> 8;
    const int tt  = t & 255;
    const int row = blockIdx.x * 2 + sub;

    float4 x = ((const float4*)a)[(size_t)row * 256 + tt];
    if (r) {
        float4 y = ((const float4*)r)[(size_t)row * 256 + tt];
        x.x += y.x; x.y += y.y; x.z += y.z; x.w += y.w;
    }
    float s  = x.x + x.y + x.z + x.w;
    float ss = x.x*x.x + x.y*x.y + x.z*x.z + x.w*x.w;
    #pragma unroll
    for (int off = 16; off; off >>= 1) {
        s  += __shfl_xor_sync(0xffffffffu, s,  off);
        ss += __shfl_xor_sync(0xffffffffu, ss, off);
    }
    __shared__ float wsum[16], wsq[16];
    int warp = t >> 5, lane = t & 31;
    if (lane == 0) { wsum[warp] = s; wsq[warp] = ss; }
    __syncthreads();
    s = 0.f; ss = 0.f;
    #pragma unroll
    for (int i = 0; i < 8; i++) {
        s  += wsum[sub * 8 + i];
        ss += wsq [sub * 8 + i];
    }
    float mean = s * (1.f/1024.f);
    float var  = ss * (1.f/1024.f) - mean*mean;
    float rstd = rsqrtf(var + 1e-5f);
    float4 gg = ((const float4*)g)[tt];
    float4 bb = ((const float4*)be)[tt];
    float4 o;
    o.x = (x.x - mean)*rstd*gg.x + bb.x;
    o.y = (x.y - mean)*rstd*gg.y + bb.y;
    o.z = (x.z - mean)*rstd*gg.z + bb.z;
    o.w = (x.w - mean)*rstd*gg.w + bb.w;
    ((float4*)out)[(size_t)row * 256 + tt] = o;
    if (WR) {
        float4 q;
        q.x = rnd32(o.x); q.y = rnd32(o.y); q.z = rnd32(o.z); q.w = rnd32(o.w);
        ((float4*)outr)[(size_t)row * 256 + tt] = q;
    }
}

// ---------------- launch ----------------
extern "C" void kernel_launch(void* const* d_in, const int* in_sizes, int n_in,
                              void* d_out, int out_size) {
    (void)in_sizes; (void)n_in; (void)out_size;
    const int*   x    = (const int*)  d_in[0];
    const int*   mask = (const int*)  d_in[1];
    const float* emb  = (const float*)d_in[2];
    const float* wq   = (const float*)d_in[3];
    const float* bq   = (const float*)d_in[4];
    const float* wk   = (const float*)d_in[5];
    const float* bk   = (const float*)d_in[6];
    const float* wv   = (const float*)d_in[7];
    const float* bv   = (const float*)d_in[8];
    const float* wo   = (const float*)d_in[9];
    const float* bo   = (const float*)d_in[10];
    const float* w1   = (const float*)d_in[11];
    const float* b1   = (const float*)d_in[12];
    const float* w2   = (const float*)d_in[13];
    const float* b2   = (const float*)d_in[14];
    const float* g1   = (const float*)d_in[15];
    const float* be1  = (const float*)d_in[16];
    const float* g2   = (const float*)d_in[17];
    const float* be2  = (const float*)d_in[18];
    const float* gf   = (const float*)d_in[19];
    const float* bf   = (const float*)d_in[20];
    float* out = (float*)d_out;

    float *gh, *ghr, *gq, *gk, *gv, *gctx, *gp, *gff;
    float *cwq, *cwk, *cwv, *cwo, *cw1, *cw2;
    cudaGetSymbolAddress((void**)&gh,   g_h);
    cudaGetSymbolAddress((void**)&ghr,  g_hr);
    cudaGetSymbolAddress((void**)&gq,   g_q);
    cudaGetSymbolAddress((void**)&gk,   g_k);
    cudaGetSymbolAddress((void**)&gv,   g_v);
    cudaGetSymbolAddress((void**)&gctx, g_ctx);
    cudaGetSymbolAddress((void**)&gp,   g_p);
    cudaGetSymbolAddress((void**)&gff,  g_ff);
    cudaGetSymbolAddress((void**)&cwq,  g_cwq);
    cudaGetSymbolAddress((void**)&cwk,  g_cwk);
    cudaGetSymbolAddress((void**)&cwv,  g_cwv);
    cudaGetSymbolAddress((void**)&cwo,  g_cwo);
    cudaGetSymbolAddress((void**)&cw1,  g_cw1);
    cudaGetSymbolAddress((void**)&cw2,  g_cw2);

    cudaFuncSetAttribute(attn_mma,
        cudaFuncAttributeMaxDynamicSharedMemorySize, ATTN_SMEM);
    cudaFuncSetAttribute(gemm_tf32<0,0>,
        cudaFuncAttributeMaxDynamicSharedMemorySize, GEMM_SMEM_BYTES);
    cudaFuncSetAttribute(gemm_tf32<0,1>,
        cudaFuncAttributeMaxDynamicSharedMemorySize, GEMM_SMEM_BYTES);
    cudaFuncSetAttribute(gemm_tf32<1,1>,
        cudaFuncAttributeMaxDynamicSharedMemorySize, GEMM_SMEM_BYTES);
    cudaFuncSetAttribute(gemm_qkv,
        cudaFuncAttributeMaxDynamicSharedMemorySize, GEMM_SMEM_BYTES);

    const int nDD = L_ * D_ * D_ / 4, nDF = L_ * D_ * DFF_ / 4;
    round6_kernel<<<dim3((nDF + 255) / 256, 6), 256>>>(
        wq, wk, wv, wo, w1, w2, cwq, cwk, cwv, cwo, cw1, cw2, nDD, nDF);

    embed_kernel<<<(BS_ * D_) / 256, 256>>>(x, emb, gh, ghr);

    for (int l = 0; l < L_; l++) {
        const size_t wOff = (size_t)l * D_ * D_;
        const size_t fOff = (size_t)l * D_ * DFF_;
        gemm_qkv<<<dim3(8, 64, 3), 256, GEMM_SMEM_BYTES>>>(
            ghr, cwq + wOff, bq + l * D_, cwk + wOff, bk + l * D_,
            cwv + wOff, bv + l * D_, gq, gk, gv);
        attn_mma<<<dim3(S_ / 128, H_, B_), 256, ATTN_SMEM>>>(
            gq, gk, gv, mask, gctx);
        gemm_tf32<0,0><<<dim3(8, 64), 256, GEMM_SMEM_BYTES>>>(
            gctx, cwo + wOff, bo + l * D_, gp, D_, D_);
        ln_kernel<1><<<BS_ / 2, 512>>>(gh, gp, g1 + l * D_, be1 + l * D_,
                                       gh, ghr);
        gemm_tf32<1,1><<<dim3(32, 64), 256, GEMM_SMEM_BYTES>>>(
            ghr, cw1 + fOff, b1 + l * DFF_, gff, DFF_, D_);
        gemm_tf32<0,0><<<dim3(8, 64), 256, GEMM_SMEM_BYTES>>>(
            gff, cw2 + fOff, b2 + l * D_, gp, D_, DFF_);
        ln_kernel<1><<<BS_ / 2, 512>>>(gh, gp, g2 + l * D_, be2 + l * D_,
                                       gh, ghr);
    }
    ln_kernel<0><<<BS_ / 2, 512>>>(gh, nullptr, gf, bf, out, nullptr);
}